// round 7
// baseline (speedup 1.0000x reference)
#include <cuda_runtime.h>
#include <cstdint>

#define D 128
#define C 64
#define EPSF 1e-5f
#define TGT 16              // targets per CTA -> grid = 16384/16 = 1024
#define XS_STRIDE 132       // pad: conflict-free LDS.128 at 16-row stride

// q[c][j] = EPS - prototype[c][j]   (device scratch; allocations forbidden)
__device__ float g_q[C * D];

__device__ __forceinline__ void add_f32x2(unsigned long long& d,
                                          unsigned long long a,
                                          unsigned long long b) {
    asm("add.rn.f32x2 %0, %1, %2;" : "=l"(d) : "l"(a), "l"(b));
}
__device__ __forceinline__ void fma_f32x2(unsigned long long& d,
                                          unsigned long long a,
                                          unsigned long long b) {
    asm("fma.rn.f32x2 %0, %1, %2, %0;" : "+l"(d) : "l"(a), "l"(b));
}

// ---------------------------------------------------------------------------
// Kernel 1 (unchanged, R5-proven): one CTA per class; gather row list,
// coalesced register accumulation, writes q = EPS - sum/cnt'. CTA0 zeroes out.
// ---------------------------------------------------------------------------
__global__ __launch_bounds__(256) void k_accum(const float* __restrict__ x,
                                               const int* __restrict__ y,
                                               float* __restrict__ out,
                                               int m) {
    __shared__ unsigned short list[4096];
    __shared__ int cnt;
    __shared__ float partial[D];

    int tid = threadIdx.x;
    int c   = blockIdx.x;
    if (tid == 0) cnt = 0;
    if (c == 0 && tid == 0) out[0] = 0.0f;
    __syncthreads();

    for (int i = tid; i < m; i += 256) {
        if (y[i] == c) {
            int p = atomicAdd(&cnt, 1);
            if (p < 4096) list[p] = (unsigned short)i;
        }
    }
    __syncthreads();
    int n = cnt < 4096 ? cnt : 4096;

    int j    = tid & (D - 1);
    int half = tid >> 7;
    float acc = 0.0f;
#pragma unroll 4
    for (int k = half; k < n; k += 2) {
        acc += x[(size_t)list[k] * D + j];
    }
    if (half == 1) partial[j] = acc;
    __syncthreads();
    if (half == 0) {
        float tot = acc + partial[j];
        float fc  = (n == 0) ? 1.0f : (float)n;
        g_q[c * D + j] = EPSF - tot / fc;
    }
}

// ---------------------------------------------------------------------------
// Kernel 2: distances + log_softmax + NLL. Packed f32x2 mainloop (proven R6).
// block 256 = 16 targets x 16 class-groups of 4 classes.
// x staged in smem (8.4KB -> up to 8 CTAs/SM, ~86% occ at grid 1024).
// q read via LDG (32KB, L1-resident; 2 distinct addrs per warp-load).
// ---------------------------------------------------------------------------
__global__ __launch_bounds__(256, 8) void k_loss(const float* __restrict__ x,
                                                 const int* __restrict__ y,
                                                 float* __restrict__ out,
                                                 int m) {
    __shared__ float xs[TGT * XS_STRIDE];
    __shared__ float spmax[16 * TGT];
    __shared__ float spsum[16 * TGT];
    __shared__ float sdy[TGT];
    __shared__ float red[TGT];

    int tid = threadIdx.x;
    int i0  = blockIdx.x * TGT;

    // stage x target tile (coalesced float4): 16 rows x 128
    const float4* xg = (const float4*)(x + (size_t)(m + i0) * D);
    for (int idx = tid; idx < TGT * (D / 4); idx += 256) {
        int r  = idx >> 5;
        int c4 = idx & 31;
        *(float4*)&xs[r * XS_STRIDE + c4 * 4] = xg[r * (D / 4) + c4];
    }
    __syncthreads();

    int tgt = tid & (TGT - 1);
    int cg  = tid >> 4;                       // 0..15, 4 classes each
    const float* qb = g_q + cg * 4 * D;       // global, L1-cached
    const ulonglong2* xrow = (const ulonglong2*)&xs[tgt * XS_STRIDE];

    unsigned long long accA[4], accB[4];
#pragma unroll
    for (int k = 0; k < 4; k++) { accA[k] = 0ull; accB[k] = 0ull; }

    const unsigned long long ABS2 = 0x7FFFFFFF7FFFFFFFull;

    for (int j4 = 0; j4 < D / 4; j4++) {
        ulonglong2 xv = xrow[j4];
#pragma unroll
        for (int cc = 0; cc < 4; cc++) {
            ulonglong2 qv = *(const ulonglong2*)(qb + cc * D + j4 * 4);
            unsigned long long t01, t23;
            add_f32x2(t01, xv.x, qv.x);            // t = x + (EPS - p)
            add_f32x2(t23, xv.y, qv.y);
            fma_f32x2(accA[cc], t01, t01 & ABS2);  // acc += t * |t|
            fma_f32x2(accB[cc], t23, t23 & ABS2);
        }
    }

    // unpack, partial softmax over this thread's 4 classes
    float dist[4];
    float pm = -1e30f;
#pragma unroll
    for (int cc = 0; cc < 4; cc++) {
        unsigned long long a = accA[cc];
        unsigned long long b = accB[cc];
        float s = __uint_as_float((unsigned)(a & 0xFFFFFFFFull))
                + __uint_as_float((unsigned)(a >> 32))
                + __uint_as_float((unsigned)(b & 0xFFFFFFFFull))
                + __uint_as_float((unsigned)(b >> 32));
        float dv = s * (-1.0f / (float)D);
        dist[cc] = dv;
        pm = fmaxf(pm, dv);
    }
    spmax[cg * TGT + tgt] = pm;
    __syncthreads();

    float gmax = -1e30f;
#pragma unroll
    for (int k = 0; k < 16; k++) gmax = fmaxf(gmax, spmax[k * TGT + tgt]);

    float se = 0.0f;
#pragma unroll
    for (int cc = 0; cc < 4; cc++) se += __expf(dist[cc] - gmax);
    spsum[cg * TGT + tgt] = se;

    int yc = y[m + i0 + tgt];
    if ((yc >> 2) == cg) sdy[tgt] = dist[yc & 3];
    __syncthreads();

    if (tid < TGT) {
        float tot = 0.0f;
#pragma unroll
        for (int k = 0; k < 16; k++) tot += spsum[k * TGT + tid];
        red[tid] = -(sdy[tid] - gmax - __logf(tot));
    }
    __syncthreads();

    if (tid == 0) {
        float s = 0.0f;
#pragma unroll
        for (int k = 0; k < TGT; k++) s += red[k];
        atomicAdd(out, s / (float)m);
    }
}

// ---------------------------------------------------------------------------
// launch
// ---------------------------------------------------------------------------
extern "C" void kernel_launch(void* const* d_in, const int* in_sizes, int n_in,
                              void* d_out, int out_size) {
    const float* x = (const float*)d_in[0];
    const int*   y = (const int*)d_in[1];
    int n = in_sizes[1];
    int m = n / 2;
    float* out = (float*)d_out;

    k_accum<<<C, 256>>>(x, y, out, m);
    k_loss<<<m / TGT, 256>>>(x, y, out, m);
}

// round 9
// speedup vs baseline: 1.0734x; 1.0734x over previous
#include <cuda_runtime.h>
#include <cstdint>

#define D 128
#define C 64
#define EPSF 1e-5f
#define TGT 32              // targets per CTA -> grid = 16384/32 = 512
#define NCG 16              // class groups = warps per block
#define CPG 4               // classes per group
#define XS_STRIDE 132       // pad: conflict-free LDS.128

// q[c][j] = EPS - prototype[c][j]   (device scratch; allocations forbidden)
__device__ float g_q[C * D];

__device__ __forceinline__ void add_f32x2(unsigned long long& d,
                                          unsigned long long a,
                                          unsigned long long b) {
    asm("add.rn.f32x2 %0, %1, %2;" : "=l"(d) : "l"(a), "l"(b));
}
__device__ __forceinline__ void fma_f32x2(unsigned long long& d,
                                          unsigned long long a,
                                          unsigned long long b) {
    asm("fma.rn.f32x2 %0, %1, %2, %0;" : "+l"(d) : "l"(a), "l"(b));
}

// ---------------------------------------------------------------------------
// Kernel 1 (unchanged, R5-proven): one CTA per class; gather row list,
// coalesced register accumulation, writes q = EPS - sum/cnt'. CTA0 zeroes out.
// ---------------------------------------------------------------------------
__global__ __launch_bounds__(256) void k_accum(const float* __restrict__ x,
                                               const int* __restrict__ y,
                                               float* __restrict__ out,
                                               int m) {
    __shared__ unsigned short list[4096];
    __shared__ int cnt;
    __shared__ float partial[D];

    int tid = threadIdx.x;
    int c   = blockIdx.x;
    if (tid == 0) cnt = 0;
    if (c == 0 && tid == 0) out[0] = 0.0f;
    __syncthreads();

    for (int i = tid; i < m; i += 256) {
        if (y[i] == c) {
            int p = atomicAdd(&cnt, 1);
            if (p < 4096) list[p] = (unsigned short)i;
        }
    }
    __syncthreads();
    int n = cnt < 4096 ? cnt : 4096;

    int j    = tid & (D - 1);
    int half = tid >> 7;
    float acc = 0.0f;
#pragma unroll 4
    for (int k = half; k < n; k += 2) {
        acc += x[(size_t)list[k] * D + j];
    }
    if (half == 1) partial[j] = acc;
    __syncthreads();
    if (half == 0) {
        float tot = acc + partial[j];
        float fc  = (n == 0) ? 1.0f : (float)n;
        g_q[c * D + j] = EPSF - tot / fc;
    }
}

// ---------------------------------------------------------------------------
// Kernel 2: distances + log_softmax + NLL. Packed f32x2 mainloop.
// block 512 = 16 warps; warp w handles classes [4w, 4w+4), lane = target.
// q in DYNAMIC smem, warp-uniform address -> pure broadcast LDS.
// x in DYNAMIC smem, stride 132 -> conflict-free LDS.128.
// dyn smem ~49.9KB + ~2.3KB static -> 4 CTAs/SM cap; grid 512 -> ~86% occ.
// ---------------------------------------------------------------------------
extern __shared__ float dynsmem[];

__global__ __launch_bounds__(512, 4) void k_loss(const float* __restrict__ x,
                                                 const int* __restrict__ y,
                                                 float* __restrict__ out,
                                                 int m) {
    float* xs = dynsmem;                   // TGT * 132 = 16.9 KB
    float* qs = xs + TGT * XS_STRIDE;      // C * D     = 32 KB
    __shared__ float spmax[NCG * TGT];
    __shared__ float spsum[NCG * TGT];
    __shared__ float sdy[TGT];

    int tid = threadIdx.x;
    int i0  = blockIdx.x * TGT;

    // stage x target tile (coalesced float4): 32 rows x 128
    const float4* xg = (const float4*)(x + (size_t)(m + i0) * D);
    for (int idx = tid; idx < TGT * (D / 4); idx += 512) {
        int r  = idx >> 5;
        int c4 = idx & 31;
        *(float4*)&xs[r * XS_STRIDE + c4 * 4] = xg[r * (D / 4) + c4];
    }
    // stage q (L2-resident after first CTAs)
    for (int idx = tid; idx < C * D / 4; idx += 512) {
        ((float4*)qs)[idx] = ((const float4*)g_q)[idx];
    }
    __syncthreads();

    int tgt = tid & 31;                 // lane = target
    int cg  = tid >> 5;                 // warp = class group (uniform per warp)
    const ulonglong2* xrow = (const ulonglong2*)&xs[tgt * XS_STRIDE];
    const float* qb = &qs[cg * CPG * D];

    unsigned long long accA[CPG], accB[CPG];
#pragma unroll
    for (int k = 0; k < CPG; k++) { accA[k] = 0ull; accB[k] = 0ull; }

    const unsigned long long ABS2 = 0x7FFFFFFF7FFFFFFFull;

    for (int j4 = 0; j4 < D / 4; j4++) {
        ulonglong2 xv = xrow[j4];
#pragma unroll
        for (int cc = 0; cc < CPG; cc++) {
            ulonglong2 qv = *(const ulonglong2*)&qb[cc * D + j4 * 4];  // broadcast
            unsigned long long t01, t23;
            add_f32x2(t01, xv.x, qv.x);            // t = x + (EPS - p)
            add_f32x2(t23, xv.y, qv.y);
            fma_f32x2(accA[cc], t01, t01 & ABS2);  // acc += t * |t|
            fma_f32x2(accB[cc], t23, t23 & ABS2);
        }
    }

    // unpack, partial softmax over this warp's 4 classes
    float dist[CPG];
    float pm = -1e30f;
#pragma unroll
    for (int cc = 0; cc < CPG; cc++) {
        unsigned long long a = accA[cc];
        unsigned long long b = accB[cc];
        float s = __uint_as_float((unsigned)(a & 0xFFFFFFFFull))
                + __uint_as_float((unsigned)(a >> 32))
                + __uint_as_float((unsigned)(b & 0xFFFFFFFFull))
                + __uint_as_float((unsigned)(b >> 32));
        float dv = s * (-1.0f / (float)D);
        dist[cc] = dv;
        pm = fmaxf(pm, dv);
    }
    spmax[cg * TGT + tgt] = pm;
    __syncthreads();

    float gmax = -1e30f;
#pragma unroll
    for (int k = 0; k < NCG; k++) gmax = fmaxf(gmax, spmax[k * TGT + tgt]);

    float se = 0.0f;
#pragma unroll
    for (int cc = 0; cc < CPG; cc++) se += __expf(dist[cc] - gmax);
    spsum[cg * TGT + tgt] = se;

    int yc = y[m + i0 + tgt];
    if ((yc >> 2) == cg) sdy[tgt] = dist[yc & 3];
    __syncthreads();

    if (tid < TGT) {
        float tot = 0.0f;
#pragma unroll
        for (int k = 0; k < NCG; k++) tot += spsum[k * TGT + tid];
        float v = -(sdy[tid] - gmax - __logf(tot));
        // warp-reduce the 32 per-target losses, single atomic per CTA
#pragma unroll
        for (int off = 16; off > 0; off >>= 1)
            v += __shfl_xor_sync(0xFFFFFFFFu, v, off);
        if (tid == 0) atomicAdd(out, v / (float)m);
    }
}

// ---------------------------------------------------------------------------
// launch
// ---------------------------------------------------------------------------
extern "C" void kernel_launch(void* const* d_in, const int* in_sizes, int n_in,
                              void* d_out, int out_size) {
    const float* x = (const float*)d_in[0];
    const int*   y = (const int*)d_in[1];
    int n = in_sizes[1];
    int m = n / 2;
    float* out = (float*)d_out;

    k_accum<<<C, 256>>>(x, y, out, m);

    size_t dynbytes = (size_t)(TGT * XS_STRIDE + C * D) * sizeof(float);
    cudaFuncSetAttribute(k_loss, cudaFuncAttributeMaxDynamicSharedMemorySize,
                         (int)dynbytes);
    k_loss<<<m / TGT, 512, dynbytes>>>(x, y, out, m);
}

// round 10
// speedup vs baseline: 1.3272x; 1.2365x over previous
#include <cuda_runtime.h>
#include <cstdint>

#define D 128
#define C 64
#define EPSF 1e-5f
#define TGT 32              // targets per CTA -> grid = 16384/32 = 512
#define XS_STRIDE 132       // 16B-aligned row stride

// q[c][j] = EPS - prototype[c][j]   (device scratch; allocations forbidden)
__device__ float g_q[C * D];

__device__ __forceinline__ void add_f32x2(unsigned long long& d,
                                          unsigned long long a,
                                          unsigned long long b) {
    asm("add.rn.f32x2 %0, %1, %2;" : "=l"(d) : "l"(a), "l"(b));
}
__device__ __forceinline__ void unpack2(float& lo, float& hi,
                                        unsigned long long v) {
    asm("mov.b64 {%0, %1}, %2;" : "=f"(lo), "=f"(hi) : "l"(v));
}

// ---------------------------------------------------------------------------
// Kernel 1: one CTA per class; gather row list (unrolled scan), coalesced
// register accumulation, writes q = EPS - sum/cnt'. CTA0 zeroes out.
// ---------------------------------------------------------------------------
__global__ __launch_bounds__(256) void k_accum(const float* __restrict__ x,
                                               const int* __restrict__ y,
                                               float* __restrict__ out,
                                               int m) {
    __shared__ unsigned short list[4096];
    __shared__ int cnt;
    __shared__ float partial[D];

    int tid = threadIdx.x;
    int c   = blockIdx.x;
    if (tid == 0) cnt = 0;
    if (c == 0 && tid == 0) out[0] = 0.0f;
    __syncthreads();

#pragma unroll 8
    for (int i = tid; i < m; i += 256) {
        if (y[i] == c) {
            int p = atomicAdd(&cnt, 1);
            if (p < 4096) list[p] = (unsigned short)i;
        }
    }
    __syncthreads();
    int n = cnt < 4096 ? cnt : 4096;

    int j    = tid & (D - 1);
    int half = tid >> 7;
    float acc = 0.0f;
#pragma unroll 4
    for (int k = half; k < n; k += 2) {
        acc += x[(size_t)list[k] * D + j];
    }
    if (half == 1) partial[j] = acc;
    __syncthreads();
    if (half == 0) {
        float tot = acc + partial[j];
        float fc  = (n == 0) ? 1.0f : (float)n;
        g_q[c * D + j] = EPSF - tot / fc;
    }
}

// ---------------------------------------------------------------------------
// Kernel 2: distances + log_softmax + NLL.
// block 256 = 8 warps. Warp w covers classes [8w, 8w+8) and all 32 targets:
//   lane = sub*16 + trow;  sub picks 4 of the 8 classes, trow picks a target
//   row; each lane processes targets {trow, trow+16} and 4 classes.
// -> per j4 per warp: 4 q-LDS (2-addr broadcast) + 2 x-LDS serve 32 elements.
// Math: FADD2 (packed) + FFMA with |src| modifier = 1.5 instr/element.
// dyn smem 48.5KB -> 4 CTAs/SM cap; grid 512 -> ~3.5 resident.
// ---------------------------------------------------------------------------
extern __shared__ float dynsmem[];

__global__ __launch_bounds__(256, 4) void k_loss(const float* __restrict__ x,
                                                 const int* __restrict__ y,
                                                 float* __restrict__ out,
                                                 int m) {
    float* xs = dynsmem;                   // 32 * 132 = 16.5 KB
    float* qs = xs + TGT * XS_STRIDE;      // 64 * 128 = 32 KB
    __shared__ float spmax[16 * TGT];
    __shared__ float spsum[16 * TGT];
    __shared__ float sdy[TGT];

    int tid = threadIdx.x;
    int i0  = blockIdx.x * TGT;

    // stage x target tile (32 x 128, coalesced float4)
    const float4* xg = (const float4*)(x + (size_t)(m + i0) * D);
#pragma unroll
    for (int k = 0; k < 4; k++) {
        int idx = tid + k * 256;          // 0..1023
        int r = idx >> 5, c4 = idx & 31;
        *(float4*)&xs[r * XS_STRIDE + c4 * 4] = xg[r * 32 + c4];
    }
    // stage q (L2-resident after first CTAs)
#pragma unroll
    for (int k = 0; k < 8; k++) {
        int idx = tid + k * 256;          // 0..2047 float4
        ((float4*)qs)[idx] = ((const float4*)g_q)[idx];
    }
    __syncthreads();

    int lane = tid & 31;
    int cg   = tid >> 5;                  // warp id 0..7
    int sub  = lane >> 4;                 // 0/1: class sub-group
    int trow = lane & 15;                 // target row 0..15
    int cb   = cg * 8 + sub * 4;          // first of this lane's 4 classes
    int sidx = cg * 2 + sub;              // class-subset index 0..15

    const ulonglong2* xr0 = (const ulonglong2*)&xs[trow * XS_STRIDE];
    const ulonglong2* xr1 = (const ulonglong2*)&xs[(trow + 16) * XS_STRIDE];
    const float* qb = &qs[cb * D];

    float acc[4][2];
#pragma unroll
    for (int k = 0; k < 4; k++) { acc[k][0] = 0.0f; acc[k][1] = 0.0f; }

#pragma unroll 2
    for (int j4 = 0; j4 < D / 4; j4++) {
        ulonglong2 xv0 = xr0[j4];
        ulonglong2 xv1 = xr1[j4];
#pragma unroll
        for (int cc = 0; cc < 4; cc++) {
            ulonglong2 qv = *(const ulonglong2*)&qb[cc * D + j4 * 4];
            unsigned long long a, b, e, f;
            add_f32x2(a, xv0.x, qv.x);     // target 0, dims 0-1
            add_f32x2(b, xv0.y, qv.y);     // target 0, dims 2-3
            add_f32x2(e, xv1.x, qv.x);     // target 1, dims 0-1
            add_f32x2(f, xv1.y, qv.y);     // target 1, dims 2-3
            float lo, hi;
            unpack2(lo, hi, a);
            acc[cc][0] = fmaf(lo, fabsf(lo), acc[cc][0]);
            acc[cc][0] = fmaf(hi, fabsf(hi), acc[cc][0]);
            unpack2(lo, hi, b);
            acc[cc][0] = fmaf(lo, fabsf(lo), acc[cc][0]);
            acc[cc][0] = fmaf(hi, fabsf(hi), acc[cc][0]);
            unpack2(lo, hi, e);
            acc[cc][1] = fmaf(lo, fabsf(lo), acc[cc][1]);
            acc[cc][1] = fmaf(hi, fabsf(hi), acc[cc][1]);
            unpack2(lo, hi, f);
            acc[cc][1] = fmaf(lo, fabsf(lo), acc[cc][1]);
            acc[cc][1] = fmaf(hi, fabsf(hi), acc[cc][1]);
        }
    }

    // partial softmax over this lane's 4 classes, for both targets
    float dist[4][2];
    float pm0 = -1e30f, pm1 = -1e30f;
#pragma unroll
    for (int cc = 0; cc < 4; cc++) {
        float d0 = acc[cc][0] * (-1.0f / (float)D);
        float d1 = acc[cc][1] * (-1.0f / (float)D);
        dist[cc][0] = d0; dist[cc][1] = d1;
        pm0 = fmaxf(pm0, d0);
        pm1 = fmaxf(pm1, d1);
    }
    spmax[sidx * TGT + trow]      = pm0;
    spmax[sidx * TGT + trow + 16] = pm1;
    __syncthreads();

    float g0 = -1e30f, g1 = -1e30f;
#pragma unroll
    for (int k = 0; k < 16; k++) {
        g0 = fmaxf(g0, spmax[k * TGT + trow]);
        g1 = fmaxf(g1, spmax[k * TGT + trow + 16]);
    }
    float se0 = 0.0f, se1 = 0.0f;
#pragma unroll
    for (int cc = 0; cc < 4; cc++) {
        se0 += __expf(dist[cc][0] - g0);
        se1 += __expf(dist[cc][1] - g1);
    }
    spsum[sidx * TGT + trow]      = se0;
    spsum[sidx * TGT + trow + 16] = se1;

    int yc0 = y[m + i0 + trow];
    if (yc0 >= cb && yc0 < cb + 4) sdy[trow] = dist[yc0 - cb][0];
    int yc1 = y[m + i0 + trow + 16];
    if (yc1 >= cb && yc1 < cb + 4) sdy[trow + 16] = dist[yc1 - cb][1];
    __syncthreads();

    if (tid < TGT) {
        float tot = 0.0f, gm = -1e30f;
#pragma unroll
        for (int k = 0; k < 16; k++) {
            tot += spsum[k * TGT + tid];
            gm   = fmaxf(gm, spmax[k * TGT + tid]);
        }
        float v = -(sdy[tid] - gm - __logf(tot));
#pragma unroll
        for (int off = 16; off > 0; off >>= 1)
            v += __shfl_xor_sync(0xFFFFFFFFu, v, off);
        if (tid == 0) atomicAdd(out, v / (float)m);
    }
}

// ---------------------------------------------------------------------------
// launch
// ---------------------------------------------------------------------------
extern "C" void kernel_launch(void* const* d_in, const int* in_sizes, int n_in,
                              void* d_out, int out_size) {
    const float* x = (const float*)d_in[0];
    const int*   y = (const int*)d_in[1];
    int n = in_sizes[1];
    int m = n / 2;
    float* out = (float*)d_out;

    k_accum<<<C, 256>>>(x, y, out, m);

    size_t dynbytes = (size_t)(TGT * XS_STRIDE + C * D) * sizeof(float);
    cudaFuncSetAttribute(k_loss, cudaFuncAttributeMaxDynamicSharedMemorySize,
                         (int)dynbytes);
    k_loss<<<m / TGT, 256, dynbytes>>>(x, y, out, m);
}